// round 16
// baseline (speedup 1.0000x reference)
#include <cuda_runtime.h>
#include <cuda_fp16.h>
#include <math.h>
#include <stdint.h>

#define BB   128
#define TT   256
#define IN   512
#define HH   1024
#define OUT  512
#define NG   4096
#define INH  1536
#define KC   64
#define SPAD 72        // smem row stride in fp16 elems (64 + 8 pad), 144B
#define NBLK 128       // persistent grid (1 block/SM, co-resident)
#define NGRP 16        // h-producer groups (8 blocks each)

// stage layout (bytes): A single plane + B hi/lo
#define ST_A   0
#define ST_B_H 18432                 // 128*72*2
#define ST_B_L 23040                 // +32*72*2
#define STAGE  27648
#define NSTAGE 4
#define SMEM_DYN (NSTAGE * STAGE)    // 110592

// ---------------- static device scratch (~90 MB) ------------------------------
__device__ __half g_Wrhi[(size_t)NG * INH];   // r = bx*32 + gate*8 + jl
__device__ __half g_Wrlo[(size_t)NG * INH];
__device__ float  g_biasr[NG];
__device__ __half g_hs[(size_t)BB * TT * HH];  // [b][t][j], single fp16 plane
__device__ unsigned g_ready[TT][NGRP];          // dataflow flags (zeroed per launch)

__device__ __forceinline__ float sigm(float v) { return 1.f / (1.f + expf(-v)); }

__device__ __forceinline__ void mma_f16(float* c, const uint32_t* a, const uint32_t* b) {
    asm volatile(
        "mma.sync.aligned.m16n8k16.row.col.f32.f16.f16.f32 "
        "{%0,%1,%2,%3}, {%4,%5,%6,%7}, {%8,%9}, {%0,%1,%2,%3};"
        : "+f"(c[0]), "+f"(c[1]), "+f"(c[2]), "+f"(c[3])
        : "r"(a[0]), "r"(a[1]), "r"(a[2]), "r"(a[3]), "r"(b[0]), "r"(b[1]));
}

__device__ __forceinline__ void ldm4(uint32_t* r, uint32_t addr) {
    asm volatile("ldmatrix.sync.aligned.m8n8.x4.shared.b16 {%0,%1,%2,%3}, [%4];"
        : "=r"(r[0]), "=r"(r[1]), "=r"(r[2]), "=r"(r[3]) : "r"(addr));
}

__device__ __forceinline__ void cpa(uint32_t dst, const void* src) {
    asm volatile("cp.async.cg.shared.global [%0], [%1], 16;" :: "r"(dst), "l"(src));
}
#define CP_COMMIT() asm volatile("cp.async.commit_group;")
#define CP_WAIT2()  asm volatile("cp.async.wait_group 2;")

// ---------------- conversion / init kernels -----------------------------------
__global__ void conv_w(const float* __restrict__ Wf, const float* __restrict__ Wi,
                       const float* __restrict__ Wc, const float* __restrict__ Wo)
{
    size_t idx = (size_t)blockIdx.x * 256 + threadIdx.x;   // over NG*INH
    int r = (int)(idx / INH);
    int k = (int)(idx - (size_t)r * INH);
    int bx   = r >> 5;
    int gate = (r >> 3) & 3;
    int jl   = r & 7;
    int j    = bx * 8 + jl;
    const float* W = (gate == 0) ? Wf : (gate == 1) ? Wi : (gate == 2) ? Wc : Wo;
    float v = W[(size_t)j * INH + k];
    __half hi = __float2half(v);
    g_Wrhi[idx] = hi;
    g_Wrlo[idx] = __float2half(v - __half2float(hi));
}

__global__ void conv_bias(const float* __restrict__ bf, const float* __restrict__ bi,
                          const float* __restrict__ bc, const float* __restrict__ bo)
{
    int r = blockIdx.x * 256 + threadIdx.x;
    if (r < NG) {
        int bx = r >> 5, gate = (r >> 3) & 3, jl = r & 7;
        int j = bx * 8 + jl;
        const float* b = (gate == 0) ? bf : (gate == 1) ? bi : (gate == 2) ? bc : bo;
        g_biasr[r] = b[j];
    }
}

// x -> single fp16 plane, stored in the OUTPUT buffer as scratch.
__global__ void conv_x(const float* __restrict__ x, __half* __restrict__ xh)
{
    size_t idx = (size_t)blockIdx.x * 256 + threadIdx.x;   // over BB*TT*IN
    xh[idx] = __float2half(x[idx]);
}

// zero the dataflow flags (required every launch: graph replays reuse state)
__global__ void zero_flags()
{
    int i = blockIdx.x * 256 + threadIdx.x;
    if (i < TT * NGRP) ((unsigned*)g_ready)[i] = 0u;
}

// ---------------- cp.async chunk issue ----------------------------------------
__device__ __forceinline__ void issue_chunk(
    uint32_t stage, const __half* aS,
    const __half* bH, const __half* bL,
    uint32_t saoff, uint32_t sboff)
{
    #pragma unroll
    for (int q = 0; q < 4; q++)
        cpa(stage + ST_A + saoff + q * 16, aS + q * 8);
    cpa(stage + ST_B_H + sboff, bH);
    cpa(stage + ST_B_L + sboff, bL);
}

// ---------------- fragment pipeline -------------------------------------------
struct Frags { uint32_t a[4], bh0[4], bh1[4], bl0[4], bl1[4]; };

__device__ __forceinline__ void load_frags(Frags& f, uint32_t stage, int ks,
                                           uint32_t aoffb, uint32_t b0offb, uint32_t b1offb)
{
    const uint32_t kb = (uint32_t)(ks * 32);   // ks*16 elems * 2B
    ldm4(f.a,   stage + ST_A   + aoffb + kb);
    ldm4(f.bh0, stage + ST_B_H + b0offb + kb);
    ldm4(f.bh1, stage + ST_B_H + b1offb + kb);
    ldm4(f.bl0, stage + ST_B_L + b0offb + kb);
    ldm4(f.bl1, stage + ST_B_L + b1offb + kb);
}

__device__ __forceinline__ void mma_frags(const Frags& f, float acc[4][4])
{
    mma_f16(acc[0], f.a, f.bh0 + 0); mma_f16(acc[1], f.a, f.bh0 + 2);
    mma_f16(acc[2], f.a, f.bh1 + 0); mma_f16(acc[3], f.a, f.bh1 + 2);
    mma_f16(acc[0], f.a, f.bl0 + 0); mma_f16(acc[1], f.a, f.bl0 + 2);
    mma_f16(acc[2], f.a, f.bl1 + 0); mma_f16(acc[3], f.a, f.bl1 + 2);
}

// MMA over one chunk (4 k16-steps) with 2-deep register frag prefetch.
__device__ __forceinline__ void mma_stage(uint32_t stage,
                                          uint32_t aoffb, uint32_t b0offb, uint32_t b1offb,
                                          float acc[4][4])
{
    Frags f0, f1;
    load_frags(f0, stage, 0, aoffb, b0offb, b1offb);
    #pragma unroll
    for (int ks = 0; ks < 4; ks++) {
        Frags& cur = (ks & 1) ? f1 : f0;
        Frags& nxt = (ks & 1) ? f0 : f1;
        if (ks < 3)
            load_frags(nxt, stage, ks + 1, aoffb, b0offb, b1offb);
        mma_frags(cur, acc);
    }
}

// ---------------- persistent recurrent kernel --------------------------------
// Dataflow-synchronized: no global barrier. h-chunk g of step t gates on
// g_ready[t-1][g] == 8 (its 8 producer blocks), checked by tid 0 three chunks
// ahead of use, under the existing per-chunk __syncthreads.
__global__ void __launch_bounds__(256, 1) k_persist(const __half* __restrict__ xh)
{
    extern __shared__ char smem[];
    __shared__ float bias_s[32];

    const int tid  = threadIdx.x;
    const int w    = tid >> 5;
    const int lane = tid & 31;
    const int g    = lane >> 2;
    const int t2   = lane & 3;
    const int n0   = blockIdx.x * 32;
    const int j0   = blockIdx.x * 8;
    const int grp  = blockIdx.x >> 3;            // this block's producer group

    const int arow  = tid >> 1;
    const int ahalf = (tid & 1) * 32;            // elems
    const int brow  = tid >> 3;
    const int bcol  = (tid & 7) * 8;             // elems
    const uint32_t saoff = (uint32_t)((arow * SPAD + ahalf) * 2);
    const uint32_t sboff = (uint32_t)((brow * SPAD + bcol) * 2);
    const uint32_t sbase = (uint32_t)__cvta_generic_to_shared(smem);

    // fragment base offsets (bytes, ks = 0)
    const int seg = lane >> 3, lr = lane & 7;
    const int ar  = w * 16 + (seg & 1) * 8 + lr;
    const int ac  = (seg >> 1) * 8;
    const int bn  = (seg >> 1) * 8 + lr;
    const int bk  = (seg & 1) * 8;
    const uint32_t aoffb  = (uint32_t)((ar * SPAD + ac) * 2);
    const uint32_t b0offb = (uint32_t)((bn * SPAD + bk) * 2);
    const uint32_t b1offb = (uint32_t)(((bn + 16) * SPAD + bk) * 2);

    if (tid < 32) bias_s[tid] = g_biasr[n0 + tid];

    // B pointers: W rows are contiguous over k = 0..INH, so chunk idx (0..23)
    // always reads bWH/bWL + idx*KC.
    const __half* bWH = g_Wrhi + (size_t)(n0 + brow) * INH + bcol;
    const __half* bWL = g_Wrlo + (size_t)(n0 + brow) * INH + bcol;

    float creg[2][2];
    creg[0][0] = creg[0][1] = creg[1][0] = creg[1][1] = 0.f;

    for (int t = 0; t < TT; t++) {
        const int nch = (t == 0) ? (IN / KC) : (INH / KC);   // 8 or 24

        const __half* aX = xh + ((size_t)arow * TT + t) * IN + ahalf;
        const __half* aH = g_hs + ((size_t)arow * TT + (t > 0 ? t - 1 : 0)) * HH + ahalf;

        float acc[4][4];
        #pragma unroll
        for (int nt = 0; nt < 4; nt++)
            #pragma unroll
            for (int i = 0; i < 4; i++) acc[nt][i] = 0.f;

        // prologue: chunks 0..2 (always x; 8 >= 3)
        #pragma unroll
        for (int s = 0; s < 3; s++) {
            issue_chunk(sbase + s * STAGE, aX + s * KC, bWH + s * KC, bWL + s * KC,
                        saoff, sboff);
            CP_COMMIT();
        }

        for (int c = 0; c < nch; c++) {
            CP_WAIT2();                 // chunk c landed (<=2 newer groups pending)
            const int ci = c + 3;
            if (tid == 0 && ci >= 8 && ci < nch) {
                // gate h-chunk (ci-8) on its 8 producers from step t-1
                volatile unsigned* f = &g_ready[t - 1][ci - 8];
                while (*f < 8u) {}
            }
            __syncthreads();            // orders spin result + stage (c-1)%4 reads
            if (ci < nch) {
                const __half* aSrc = (ci < 8) ? aX + ci * KC : aH + (ci - 8) * KC;
                issue_chunk(sbase + (ci & 3) * STAGE, aSrc,
                            bWH + ci * KC, bWL + ci * KC, saoff, sboff);
            }
            CP_COMMIT();                // empty group at tail keeps counts aligned
            mma_stage(sbase + (c & 3) * STAGE, aoffb, b0offb, b1offb, acc);
        }

        // ---- fused LSTM cell epilogue ----
        #pragma unroll
        for (int dr = 0; dr < 2; dr++) {
            const int b_  = w * 16 + g + dr * 8;
            const int ci0 = dr * 2;
            const int jlA = 2 * t2;

            float hn2[2];
            #pragma unroll
            for (int dc = 0; dc < 2; dc++) {
                const int jl = jlA + dc;
                const int ci = ci0 + dc;
                const float fp = acc[0][ci] + bias_s[jl];
                const float ip = acc[1][ci] + bias_s[8 + jl];
                const float cp = acc[2][ci] + bias_s[16 + jl];
                const float op = acc[3][ci] + bias_s[24 + jl];
                const float cn = sigm(fp) * creg[dr][dc] + sigm(ip) * tanhf(cp);
                creg[dr][dc] = cn;
                hn2[dc] = sigm(op) * tanhf(cn);
            }
            const size_t ho = ((size_t)b_ * TT + t) * HH + j0 + jlA;
            __half2 hp;
            hp.x = __float2half(hn2[0]);
            hp.y = __float2half(hn2[1]);
            __stcg((unsigned*)(g_hs + ho), *(const unsigned*)&hp);
        }

        // ---- publish: this block's h slice for step t is ready ----
        if (t < TT - 1) {
            __threadfence();            // order h stores before the flag
            __syncthreads();            // all threads' stores + fences done
            if (tid == 0)
                atomicAdd(&g_ready[t][grp], 1u);
        }
    }
}

// ---------------- kernel 3: out = hs @ W_out^T + b_out (fp32 SIMT) -----------
__global__ void __launch_bounds__(256, 2) k3_out(
                       const float* __restrict__ Wout,
                       const float* __restrict__ bout,
                       float* __restrict__ out)
{
    __shared__ float As[8][128];
    __shared__ float Bs[8][128];

    const int m0 = blockIdx.x * 128;
    const int n0 = blockIdx.y * 128;
    const int tid = threadIdx.x;
    const int lr = tid >> 1;
    const int lk = (tid & 1) * 4;

    const __half* Ahp = g_hs + (size_t)(m0 + lr) * HH;
    const float* Brow = Wout + (size_t)(n0 + lr) * HH;

    float acc[8][8];
    #pragma unroll
    for (int i = 0; i < 8; i++)
        #pragma unroll
        for (int j = 0; j < 8; j++) acc[i][j] = 0.f;

    const int r0 = (tid >> 4) * 8;
    const int c0 = (tid & 15) * 8;

    for (int k0 = 0; k0 < HH; k0 += 8) {
        const uint2 rh = *(const uint2*)(Ahp + k0 + lk);
        const __half2 h01 = *(const __half2*)&rh.x;
        const __half2 h23 = *(const __half2*)&rh.y;
        float4 av;
        av.x = __half2float(h01.x);
        av.y = __half2float(h01.y);
        av.z = __half2float(h23.x);
        av.w = __half2float(h23.y);
        const float4 bv = *(const float4*)(Brow + k0 + lk);
        __syncthreads();
        As[lk + 0][lr] = av.x; As[lk + 1][lr] = av.y; As[lk + 2][lr] = av.z; As[lk + 3][lr] = av.w;
        Bs[lk + 0][lr] = bv.x; Bs[lk + 1][lr] = bv.y; Bs[lk + 2][lr] = bv.z; Bs[lk + 3][lr] = bv.w;
        __syncthreads();
        #pragma unroll
        for (int k = 0; k < 8; k++) {
            float4 a0 = *(const float4*)&As[k][r0];
            float4 a1 = *(const float4*)&As[k][r0 + 4];
            float4 b0 = *(const float4*)&Bs[k][c0];
            float4 b1 = *(const float4*)&Bs[k][c0 + 4];
            float ar[8] = {a0.x, a0.y, a0.z, a0.w, a1.x, a1.y, a1.z, a1.w};
            float br[8] = {b0.x, b0.y, b0.z, b0.w, b1.x, b1.y, b1.z, b1.w};
            #pragma unroll
            for (int i = 0; i < 8; i++)
                #pragma unroll
                for (int j = 0; j < 8; j++) acc[i][j] += ar[i] * br[j];
        }
    }

    #pragma unroll
    for (int i = 0; i < 8; i++) {
        float* Crow = out + (size_t)(m0 + r0 + i) * OUT + n0;
        #pragma unroll
        for (int j = 0; j < 8; j++) Crow[c0 + j] = acc[i][j] + bout[n0 + c0 + j];
    }
}

// ---------------- launch -----------------------------------------------------
extern "C" void kernel_launch(void* const* d_in, const int* in_sizes, int n_in,
                              void* d_out, int out_size)
{
    const float* x    = (const float*)d_in[0];
    const float* Wf   = (const float*)d_in[1];
    const float* bf   = (const float*)d_in[2];
    const float* Wi   = (const float*)d_in[3];
    const float* bi   = (const float*)d_in[4];
    const float* Wc   = (const float*)d_in[5];
    const float* bc   = (const float*)d_in[6];
    const float* Wo   = (const float*)d_in[7];
    const float* bo   = (const float*)d_in[8];
    const float* Wout = (const float*)d_in[9];
    const float* bout = (const float*)d_in[10];
    float* out = (float*)d_out;

    // x fp16 plane lives in d_out as scratch; k3_out overwrites d_out at the end.
    __half* xh = (__half*)d_out;

    cudaFuncSetAttribute(k_persist, cudaFuncAttributeMaxDynamicSharedMemorySize, SMEM_DYN);

    conv_w    <<<(NG * INH) / 256, 256>>>(Wf, Wi, Wc, Wo);
    conv_bias <<<16, 256>>>(bf, bi, bc, bo);
    conv_x    <<<(BB * TT * IN) / 256, 256>>>(x, xh);
    zero_flags<<<(TT * NGRP + 255) / 256, 256>>>();

    k_persist<<<NBLK, 256, SMEM_DYN>>>(xh);

    k3_out<<<dim3((BB * TT) / 128, OUT / 128), 256>>>(Wout, bout, out);
}